// round 11
// baseline (speedup 1.0000x reference)
#include <cuda_runtime.h>
#include <cuda_fp16.h>
#include <cstdint>

#define H 256
#define NNODES 32768
#define NEDGES 524288
#define NB 32
#define NPER 1024
#define NLAYER 3

__device__ __align__(16) float g_h[NNODES * H];
__device__ __align__(16) __half g_hh[NNODES * H];         // fp16 mirror of h (gather)
__device__ __align__(16) float g_agg[NNODES * H];
__device__ __align__(16) float g_u[NNODES * H];
__device__ __align__(16) float g_v[NNODES * H];
__device__ __align__(16) __half g_msg[NEDGES * H];        // per-edge messages (fp16)
__device__ __align__(16) __half g_WhatT[NLAYER * H * H];  // [l][n][k] half
__device__ __align__(16) __half g_mw1T[NLAYER * H * H];   // [l][n][k] half
__device__ __align__(16) __half g_mw2T[NLAYER * H * H];   // [l][n][k] half
__device__ __align__(16) float g_cl[NLAYER * H];
__device__ __align__(16) float g_pool[NB * H];
__device__ __align__(16) int g_src[NEDGES];
__device__ __align__(16) int g_dst[NEDGES];
__device__ __align__(16) int g_src_s[NEDGES];             // dst-sorted src
__device__ __align__(16) float g_ea_s[NEDGES * 4];        // dst-sorted edge_attr
__device__ __align__(16) int g_deg[NNODES];
__device__ __align__(16) int g_row[NNODES + 1];           // CSR offsets by dst
__device__ __align__(16) int g_cursor[NNODES];
__device__ int g_is64;

__device__ __forceinline__ void mma_f16(float* d, const uint32_t* a, const uint32_t* b) {
    asm volatile(
        "mma.sync.aligned.m16n8k16.row.col.f32.f16.f16.f32 "
        "{%0,%1,%2,%3}, {%4,%5,%6,%7}, {%8,%9}, {%0,%1,%2,%3};"
        : "+f"(d[0]), "+f"(d[1]), "+f"(d[2]), "+f"(d[3])
        : "r"(a[0]), "r"(a[1]), "r"(a[2]), "r"(a[3]), "r"(b[0]), "r"(b[1]));
}

__device__ __forceinline__ uint32_t pack_h2(float x, float y) {
    uint32_t u;
    asm("cvt.rn.f16x2.f32 %0, %1, %2;" : "=r"(u) : "f"(y), "f"(x));
    return u;
}

#define SAW 20  // smem row stride in words: 16 half2 + 4 pad -> conflict-free frags

// ---- edge_index dtype detection + conversion ----
__global__ void detect_idx(const void* eidx) {
    if (threadIdx.x == 0) {
        const long long* p = (const long long*)eidx;
        int valid = 0;
        for (int i = 0; i < 256; i++) {
            long long v = p[i];
            if (v >= 0 && v < NNODES) valid++;
        }
        g_is64 = (valid == 256) ? 1 : 0;
    }
}

__global__ void conv_idx(const void* eidx) {
    int i = blockIdx.x * blockDim.x + threadIdx.x;
    if (i >= NEDGES) return;
    long long s, d;
    if (g_is64) {
        const long long* p = (const long long*)eidx;
        s = p[i]; d = p[NEDGES + i];
    } else {
        const int* p = (const int*)eidx;
        s = p[i]; d = p[NEDGES + i];
    }
    g_src[i] = (int)min((long long)(NNODES - 1), max(0LL, s));
    g_dst[i] = (int)min((long long)(NNODES - 1), max(0LL, d));
}

// ---- counting sort by dst ----
__global__ void zero_deg() {
    int i = blockIdx.x * blockDim.x + threadIdx.x;
    if (i < NNODES) g_deg[i] = 0;
}

__global__ void hist_kernel() {
    int i = blockIdx.x * blockDim.x + threadIdx.x;
    if (i < NEDGES) atomicAdd(&g_deg[g_dst[i]], 1);
}

__global__ void scan_kernel() {  // 1 block, 1024 threads; 32 entries each
    __shared__ int csum[1024];
    int tid = threadIdx.x;
    int base = tid * 32;
    int local[32];
    int s = 0;
#pragma unroll
    for (int j = 0; j < 32; j++) { local[j] = s; s += g_deg[base + j]; }
    csum[tid] = s;
    __syncthreads();
    if (tid == 0) {
        int r = 0;
        for (int i = 0; i < 1024; i++) { int t = csum[i]; csum[i] = r; r += t; }
    }
    __syncthreads();
    int off = csum[tid];
#pragma unroll
    for (int j = 0; j < 32; j++) {
        g_row[base + j] = off + local[j];
        g_cursor[base + j] = off + local[j];
    }
    if (tid == 0) g_row[NNODES] = NEDGES;
}

__global__ void scatter_kernel(const float* __restrict__ edge_attr) {
    int i = blockIdx.x * blockDim.x + threadIdx.x;
    if (i >= NEDGES) return;
    int d = g_dst[i];
    int pos = atomicAdd(&g_cursor[d], 1);
    g_src_s[pos] = g_src[i];
    reinterpret_cast<float4*>(g_ea_s)[pos] =
        reinterpret_cast<const float4*>(edge_attr)[i];
}

__global__ void prep_what(const float* __restrict__ em_w2, const float* __restrict__ lin_w) {
    int l = blockIdx.y, k = blockIdx.x, j = threadIdx.x;  // j = n
    __shared__ float row[H];
    row[j] = em_w2[k * H + j];
    __syncthreads();
    const float* lw = lin_w + l * H * H;
    float acc = 0.f;
#pragma unroll 8
    for (int i = 0; i < H; i++) acc += row[i] * lw[i * H + j];
    g_WhatT[(l * H + j) * H + k] = __float2half(acc);
}

__global__ void prep_mwT(const float* __restrict__ m_w1, const float* __restrict__ m_w2) {
    int n = blockIdx.x, l = blockIdx.y, k = threadIdx.x;
    g_mw1T[(l * H + n) * H + k] = __float2half(m_w1[l * H * H + k * H + n]);
    g_mw2T[(l * H + n) * H + k] = __float2half(m_w2[l * H * H + k * H + n]);
}

__global__ void prep_cl(const float* __restrict__ em_b2, const float* __restrict__ lin_w,
                        const float* __restrict__ lin_b) {
    int l = blockIdx.x, j = threadIdx.x;
    const float* lw = lin_w + l * H * H;
    float acc = lin_b[l * H + j];
#pragma unroll 8
    for (int i = 0; i < H; i++) acc += em_b2[i] * lw[i * H + j];
    g_cl[l * H + j] = acc;
}

__global__ void node_init(const float* __restrict__ x, const int* __restrict__ a,
                          const float* __restrict__ np_w, const float* __restrict__ np_b) {
    __shared__ float w[4 * H];
    int tid = threadIdx.x;
    for (int i = tid; i < 4 * H; i += 256) w[i] = np_w[i];
    __syncthreads();
    float bb = np_b[tid];
    int node0 = blockIdx.x * 8;
    for (int i = 0; i < 8; i++) {
        int node = node0 + i;
        float v = x[node * 3] * w[tid] + x[node * 3 + 1] * w[H + tid] +
                  x[node * 3 + 2] * w[2 * H + tid] + (float)a[node] * w[3 * H + tid] + bb;
        v = fmaxf(v, 0.f);
        g_h[node * H + tid] = v;
        g_hh[node * H + tid] = __float2half(v);
    }
}

__global__ void zero_pool() {
    for (int i = threadIdx.x; i < NB * H; i += 256) g_pool[i] = 0.f;
}

// msg[e] = relu(h[src] + t @ W_hat_l + c_l), t = relu(ea_s@em_w1+em_b1); fp16 out
__global__ void __launch_bounds__(256) edge_kernel(
    const float* __restrict__ em_w1, const float* __restrict__ em_b1, int layer) {
    __shared__ uint32_t sA[128 * SAW];
    __shared__ uint32_t sB[128 * SAW];
    __shared__ float s_ea[128 * 4];
    __shared__ int s_src[128];

    const int tid = threadIdx.x;
    const int wid = tid >> 5, lane = tid & 31;
    const int gid = lane >> 2, tg = lane & 3;
    const int e0 = blockIdx.x * 128, n0 = blockIdx.y * 128;
    const int wm = wid & 3, wn = wid >> 2;

    if (tid < 128) {
        reinterpret_cast<float4*>(s_ea)[tid] =
            reinterpret_cast<const float4*>(g_ea_s)[e0 + tid];
        s_src[tid] = g_src_s[e0 + tid];
    }
    const __half* Wt = g_WhatT + layer * H * H;

    float acc[2][8][4];
#pragma unroll
    for (int a = 0; a < 2; a++)
#pragma unroll
        for (int b = 0; b < 8; b++)
#pragma unroll
            for (int c = 0; c < 4; c++) acc[a][b][c] = 0.f;

    __syncthreads();

    const int kl = (tid & 15) * 2;
    const int trow0 = (tid >> 4) * 8;

    for (int c = 0; c < 8; c++) {
        {
            int kg = c * 32 + kl;
            float w0a = em_w1[kg], w1a = em_w1[H + kg], w2a = em_w1[2 * H + kg],
                  w3a = em_w1[3 * H + kg];
            float w0b = em_w1[kg + 1], w1b = em_w1[H + kg + 1],
                  w2b = em_w1[2 * H + kg + 1], w3b = em_w1[3 * H + kg + 1];
            float ba = em_b1[kg], bb2 = em_b1[kg + 1];
#pragma unroll
            for (int i = 0; i < 8; i++) {
                int r = trow0 + i;
                float e0v = s_ea[r * 4], e1v = s_ea[r * 4 + 1],
                      e2v = s_ea[r * 4 + 2], e3v = s_ea[r * 4 + 3];
                float ta = fmaf(e0v, w0a, fmaf(e1v, w1a, fmaf(e2v, w2a, fmaf(e3v, w3a, ba))));
                float tb = fmaf(e0v, w0b, fmaf(e1v, w1b, fmaf(e2v, w2b, fmaf(e3v, w3b, bb2))));
                sA[r * SAW + (kl >> 1)] = pack_h2(fmaxf(ta, 0.f), fmaxf(tb, 0.f));
            }
        }
#pragma unroll
        for (int it = 0; it < 2; it++) {
            int flat = it * 256 + tid;
            int n = flat >> 2, j = flat & 3;
            uint4 v = *reinterpret_cast<const uint4*>(Wt + (n0 + n) * H + c * 32 + j * 8);
            *reinterpret_cast<uint4*>(sB + n * SAW + j * 4) = v;
        }
        __syncthreads();
#pragma unroll
        for (int kk = 0; kk < 2; kk++) {
            uint32_t afr[2][4];
#pragma unroll
            for (int mt = 0; mt < 2; mt++) {
                int r = wm * 32 + mt * 16 + gid;
                afr[mt][0] = sA[r * SAW + kk * 8 + tg];
                afr[mt][1] = sA[(r + 8) * SAW + kk * 8 + tg];
                afr[mt][2] = sA[r * SAW + kk * 8 + tg + 4];
                afr[mt][3] = sA[(r + 8) * SAW + kk * 8 + tg + 4];
            }
#pragma unroll
            for (int nt = 0; nt < 8; nt++) {
                int n = wn * 64 + nt * 8 + gid;
                uint32_t bfr[2];
                bfr[0] = sB[n * SAW + kk * 8 + tg];
                bfr[1] = sB[n * SAW + kk * 8 + tg + 4];
                mma_f16(acc[0][nt], afr[0], bfr);
                mma_f16(acc[1][nt], afr[1], bfr);
            }
        }
        __syncthreads();
    }

    const float* clp = g_cl + layer * H;
#pragma unroll
    for (int mt = 0; mt < 2; mt++) {
        int r0 = wm * 32 + mt * 16 + gid;
#pragma unroll
        for (int nt = 0; nt < 8; nt++) {
            float a0 = acc[mt][nt][0], a1 = acc[mt][nt][1];
            float a2 = acc[mt][nt][2], a3 = acc[mt][nt][3];
            float r0v = __shfl_xor_sync(0xffffffffu, a0, 1);
            float r1v = __shfl_xor_sync(0xffffffffu, a1, 1);
            float r2v = __shfl_xor_sync(0xffffffffu, a2, 1);
            float r3v = __shfl_xor_sync(0xffffffffu, a3, 1);
            int colb = n0 + wn * 64 + nt * 8 + (tg & 2) * 2;
            int rloc = (tg & 1) ? (r0 + 8) : r0;
            float4 ev;
            if (tg & 1) { ev.x = r2v; ev.y = r3v; ev.z = a2; ev.w = a3; }
            else        { ev.x = a0;  ev.y = a1;  ev.z = r0v; ev.w = r1v; }
            int src = s_src[rloc];
            float4 cv = *reinterpret_cast<const float4*>(clp + colb);
            uint2 hraw = *reinterpret_cast<const uint2*>(g_hh + src * H + colb);
            __half2 ha = *reinterpret_cast<__half2*>(&hraw.x);
            __half2 hb = *reinterpret_cast<__half2*>(&hraw.y);
            float2 fa = __half22float2(ha), fb = __half22float2(hb);
            uint2 pk;
            pk.x = pack_h2(fmaxf(ev.x + cv.x + fa.x, 0.f),
                           fmaxf(ev.y + cv.y + fa.y, 0.f));
            pk.y = pack_h2(fmaxf(ev.z + cv.z + fb.x, 0.f),
                           fmaxf(ev.w + cv.w + fb.y, 0.f));
            *reinterpret_cast<uint2*>(g_msg + (e0 + rloc) * H + colb) = pk;
        }
    }
}

// agg[v] = sum of msg over CSR range of v (warp per node, coalesced fp16 stream)
__global__ void gather_agg() {
    int node = blockIdx.x * 8 + (threadIdx.x >> 5);
    int lane = threadIdx.x & 31;
    int c0 = lane * 8;
    float acc[8];
#pragma unroll
    for (int j = 0; j < 8; j++) acc[j] = 0.f;
    int s = g_row[node], e = g_row[node + 1];
    for (int i = s; i < e; i++) {
        uint4 v = *reinterpret_cast<const uint4*>(g_msg + i * H + c0);
        float2 f0 = __half22float2(*reinterpret_cast<__half2*>(&v.x));
        float2 f1 = __half22float2(*reinterpret_cast<__half2*>(&v.y));
        float2 f2 = __half22float2(*reinterpret_cast<__half2*>(&v.z));
        float2 f3 = __half22float2(*reinterpret_cast<__half2*>(&v.w));
        acc[0] += f0.x; acc[1] += f0.y; acc[2] += f1.x; acc[3] += f1.y;
        acc[4] += f2.x; acc[5] += f2.y; acc[6] += f3.x; acc[7] += f3.y;
    }
    float4 o0 = {acc[0], acc[1], acc[2], acc[3]};
    float4 o1 = {acc[4], acc[5], acc[6], acc[7]};
    *reinterpret_cast<float4*>(g_agg + node * H + c0) = o0;
    *reinterpret_cast<float4*>(g_agg + node * H + c0 + 4) = o1;
}

// mode 0: A=h+agg, out u=relu(A@m_w1+b1); mode 1: A=u, out v=A@m_w2+b2 (fp16 MMA)
__global__ void __launch_bounds__(256) mlp_kernel(const __half* __restrict__ BwT,
                                                  const float* __restrict__ bias, int mode) {
    __shared__ uint32_t sA[128 * SAW];
    __shared__ uint32_t sB[128 * SAW];
    const int tid = threadIdx.x;
    const int wid = tid >> 5, lane = tid & 31;
    const int gid = lane >> 2, tg = lane & 3;
    const int m0 = blockIdx.x * 128, n0 = blockIdx.y * 128;
    const int wm = wid & 3, wn = wid >> 2;

    float acc[2][8][4];
#pragma unroll
    for (int a = 0; a < 2; a++)
#pragma unroll
        for (int b = 0; b < 8; b++)
#pragma unroll
            for (int c = 0; c < 4; c++) acc[a][b][c] = 0.f;

    for (int k0 = 0; k0 < H; k0 += 32) {
#pragma unroll
        for (int it = 0; it < 4; it++) {
            int flat = it * 256 + tid;
            int r = flat >> 3, q = flat & 7;
            int cc = q * 4;
            float4 av;
            if (mode == 0) {
                float4 hv = *reinterpret_cast<const float4*>(g_h + (m0 + r) * H + k0 + cc);
                float4 gv = *reinterpret_cast<const float4*>(g_agg + (m0 + r) * H + k0 + cc);
                av.x = hv.x + gv.x; av.y = hv.y + gv.y;
                av.z = hv.z + gv.z; av.w = hv.w + gv.w;
            } else {
                av = *reinterpret_cast<const float4*>(g_u + (m0 + r) * H + k0 + cc);
            }
            uint2 pk;
            pk.x = pack_h2(av.x, av.y);
            pk.y = pack_h2(av.z, av.w);
            *reinterpret_cast<uint2*>(sA + r * SAW + q * 2) = pk;
        }
#pragma unroll
        for (int it = 0; it < 2; it++) {
            int flat = it * 256 + tid;
            int n = flat >> 2, j = flat & 3;
            uint4 v = *reinterpret_cast<const uint4*>(BwT + (n0 + n) * H + k0 + j * 8);
            *reinterpret_cast<uint4*>(sB + n * SAW + j * 4) = v;
        }
        __syncthreads();
#pragma unroll
        for (int kk = 0; kk < 2; kk++) {
            uint32_t afr[2][4];
#pragma unroll
            for (int mt = 0; mt < 2; mt++) {
                int r = wm * 32 + mt * 16 + gid;
                afr[mt][0] = sA[r * SAW + kk * 8 + tg];
                afr[mt][1] = sA[(r + 8) * SAW + kk * 8 + tg];
                afr[mt][2] = sA[r * SAW + kk * 8 + tg + 4];
                afr[mt][3] = sA[(r + 8) * SAW + kk * 8 + tg + 4];
            }
#pragma unroll
            for (int nt = 0; nt < 8; nt++) {
                int n = wn * 64 + nt * 8 + gid;
                uint32_t bfr[2];
                bfr[0] = sB[n * SAW + kk * 8 + tg];
                bfr[1] = sB[n * SAW + kk * 8 + tg + 4];
                mma_f16(acc[0][nt], afr[0], bfr);
                mma_f16(acc[1][nt], afr[1], bfr);
            }
        }
        __syncthreads();
    }

#pragma unroll
    for (int mt = 0; mt < 2; mt++) {
        int row = m0 + wm * 32 + mt * 16 + gid;
#pragma unroll
        for (int nt = 0; nt < 8; nt++) {
            int col = n0 + wn * 64 + nt * 8 + tg * 2;
            float b0v = bias[col], b1v = bias[col + 1];
            if (mode == 0) {
                float2 o0 = {fmaxf(acc[mt][nt][0] + b0v, 0.f),
                             fmaxf(acc[mt][nt][1] + b1v, 0.f)};
                *reinterpret_cast<float2*>(g_u + row * H + col) = o0;
                float2 o1 = {fmaxf(acc[mt][nt][2] + b0v, 0.f),
                             fmaxf(acc[mt][nt][3] + b1v, 0.f)};
                *reinterpret_cast<float2*>(g_u + (row + 8) * H + col) = o1;
            } else {
                float2 o0 = {acc[mt][nt][0] + b0v, acc[mt][nt][1] + b1v};
                *reinterpret_cast<float2*>(g_v + row * H + col) = o0;
                float2 o1 = {acc[mt][nt][2] + b0v, acc[mt][nt][3] + b1v};
                *reinterpret_cast<float2*>(g_v + (row + 8) * H + col) = o1;
            }
        }
    }
}

__global__ void ln_res_kernel(const float* __restrict__ ln_g_all,
                              const float* __restrict__ ln_b_all, int layer) {
    int row = blockIdx.x * 8 + (threadIdx.x >> 5);
    int lane = threadIdx.x & 31;
    int c0 = lane * 8;
    const float* vr = g_v + row * H;
    float4 v1 = *reinterpret_cast<const float4*>(vr + c0);
    float4 v2 = *reinterpret_cast<const float4*>(vr + c0 + 4);
    float s = (v1.x + v1.y) + (v1.z + v1.w) + (v2.x + v2.y) + (v2.z + v2.w);
    float ss = v1.x * v1.x + v1.y * v1.y + v1.z * v1.z + v1.w * v1.w +
               v2.x * v2.x + v2.y * v2.y + v2.z * v2.z + v2.w * v2.w;
#pragma unroll
    for (int o = 16; o > 0; o >>= 1) {
        s += __shfl_xor_sync(0xffffffffu, s, o);
        ss += __shfl_xor_sync(0xffffffffu, ss, o);
    }
    float mean = s * (1.f / H);
    float var = ss * (1.f / H) - mean * mean;
    float rstd = rsqrtf(var + 1e-5f);
    const float* gg = ln_g_all + layer * H;
    const float* bb = ln_b_all + layer * H;
    float4 g1 = *reinterpret_cast<const float4*>(gg + c0);
    float4 g2 = *reinterpret_cast<const float4*>(gg + c0 + 4);
    float4 b1 = *reinterpret_cast<const float4*>(bb + c0);
    float4 b2 = *reinterpret_cast<const float4*>(bb + c0 + 4);
    float* hr = g_h + row * H;
    float4 h1 = *reinterpret_cast<float4*>(hr + c0);
    float4 h2 = *reinterpret_cast<float4*>(hr + c0 + 4);
    h1.x += fmaxf((v1.x - mean) * rstd * g1.x + b1.x, 0.f);
    h1.y += fmaxf((v1.y - mean) * rstd * g1.y + b1.y, 0.f);
    h1.z += fmaxf((v1.z - mean) * rstd * g1.z + b1.z, 0.f);
    h1.w += fmaxf((v1.w - mean) * rstd * g1.w + b1.w, 0.f);
    h2.x += fmaxf((v2.x - mean) * rstd * g2.x + b2.x, 0.f);
    h2.y += fmaxf((v2.y - mean) * rstd * g2.y + b2.y, 0.f);
    h2.z += fmaxf((v2.z - mean) * rstd * g2.z + b2.z, 0.f);
    h2.w += fmaxf((v2.w - mean) * rstd * g2.w + b2.w, 0.f);
    *reinterpret_cast<float4*>(hr + c0) = h1;
    *reinterpret_cast<float4*>(hr + c0 + 4) = h2;
    uint4 hp;
    hp.x = pack_h2(h1.x, h1.y);
    hp.y = pack_h2(h1.z, h1.w);
    hp.z = pack_h2(h2.x, h2.y);
    hp.w = pack_h2(h2.z, h2.w);
    *reinterpret_cast<uint4*>(g_hh + row * H + c0) = hp;
}

__global__ void pool_kernel() {
    int b = blockIdx.x, ch = blockIdx.y, c = threadIdx.x;
    int base = b * NPER + ch * 128;
    float s = 0.f;
#pragma unroll 4
    for (int i = 0; i < 128; i++) s += g_h[(base + i) * H + c];
    atomicAdd(&g_pool[b * H + c], s);
}

__global__ void head_kernel(const float* __restrict__ hd_w1, const float* __restrict__ hd_b1,
                            const float* __restrict__ hd_w2, const float* __restrict__ hd_b2,
                            float* __restrict__ out) {
    __shared__ float gs[NB * H];
    __shared__ float red[8];
    int tid = threadIdx.x;
    int lane = tid & 31, wid = tid >> 5;
    for (int i = tid; i < NB * H; i += 256) gs[i] = g_pool[i] * (1.f / NPER);
    __syncthreads();
    float w2 = hd_w2[tid];
    float bb = hd_b1[tid];
    for (int b = 0; b < NB; b++) {
        float acc = bb;
#pragma unroll 8
        for (int i = 0; i < H; i++) acc += gs[b * H + i] * hd_w1[i * H + tid];
        float contrib = fmaxf(acc, 0.f) * w2;
#pragma unroll
        for (int o = 16; o > 0; o >>= 1) contrib += __shfl_xor_sync(0xffffffffu, contrib, o);
        if (lane == 0) red[wid] = contrib;
        __syncthreads();
        if (tid == 0) {
            float q = hd_b2[0];
            for (int w = 0; w < 8; w++) q += red[w];
            out[b] = q;
        }
        __syncthreads();
    }
}

extern "C" void kernel_launch(void* const* d_in, const int* in_sizes, int n_in,
                              void* d_out, int out_size) {
    const float* x         = (const float*)d_in[0];
    const float* edge_attr = (const float*)d_in[1];
    const void*  eidx      = (const void*)d_in[2];
    const int* a           = (const int*)d_in[3];
    const float* np_w  = (const float*)d_in[4];
    const float* np_b  = (const float*)d_in[5];
    const float* em_w1 = (const float*)d_in[6];
    const float* em_b1 = (const float*)d_in[7];
    const float* em_w2 = (const float*)d_in[8];
    const float* em_b2 = (const float*)d_in[9];
    const float* lin_w = (const float*)d_in[10];
    const float* lin_b = (const float*)d_in[11];
    const float* m_w1  = (const float*)d_in[12];
    const float* m_b1  = (const float*)d_in[13];
    const float* m_w2  = (const float*)d_in[14];
    const float* m_b2  = (const float*)d_in[15];
    const float* ln_g  = (const float*)d_in[16];
    const float* ln_b  = (const float*)d_in[17];
    const float* hd_w1 = (const float*)d_in[18];
    const float* hd_b1 = (const float*)d_in[19];
    const float* hd_w2 = (const float*)d_in[20];
    const float* hd_b2 = (const float*)d_in[21];
    float* out = (float*)d_out;

    __half* w1T; cudaGetSymbolAddress((void**)&w1T, g_mw1T);
    __half* w2T; cudaGetSymbolAddress((void**)&w2T, g_mw2T);

    detect_idx<<<1, 32>>>(eidx);
    conv_idx<<<NEDGES / 256, 256>>>(eidx);
    zero_deg<<<NNODES / 256, 256>>>();
    hist_kernel<<<NEDGES / 256, 256>>>();
    scan_kernel<<<1, 1024>>>();
    scatter_kernel<<<NEDGES / 256, 256>>>(edge_attr);
    prep_what<<<dim3(H, NLAYER), 256>>>(em_w2, lin_w);
    prep_mwT<<<dim3(H, NLAYER), 256>>>(m_w1, m_w2);
    prep_cl<<<NLAYER, 256>>>(em_b2, lin_w, lin_b);
    node_init<<<NNODES / 8, 256>>>(x, a, np_w, np_b);

    for (int l = 0; l < NLAYER; l++) {
        edge_kernel<<<dim3(NEDGES / 128, 2), 256>>>(em_w1, em_b1, l);
        gather_agg<<<NNODES / 8, 256>>>();
        mlp_kernel<<<dim3(NNODES / 128, 2), 256>>>(w1T + l * H * H, m_b1 + l * H, 0);
        mlp_kernel<<<dim3(NNODES / 128, 2), 256>>>(w2T + l * H * H, m_b2 + l * H, 1);
        ln_res_kernel<<<NNODES / 8, 256>>>(ln_g, ln_b, l);
    }

    zero_pool<<<1, 256>>>();
    pool_kernel<<<dim3(NB, NPER / 128), 256>>>();
    head_kernel<<<1, 256>>>(hd_w1, hd_b1, hd_w2, hd_b2, out);
}

// round 13
// speedup vs baseline: 1.1295x; 1.1295x over previous
#include <cuda_runtime.h>
#include <cuda_fp16.h>
#include <cstdint>

#define H 256
#define NNODES 32768
#define NEDGES 524288
#define NB 32
#define NPER 1024
#define NLAYER 3

__device__ __align__(16) float g_h[NNODES * H];
__device__ __align__(16) __half g_hh[NNODES * H];
__device__ __align__(16) float g_agg[NNODES * H];
__device__ __align__(16) float g_u[NNODES * H];
__device__ __align__(16) float g_v[NNODES * H];
__device__ __align__(16) __half g_WhatT[NLAYER * H * H];  // [l][n][k] half
__device__ __align__(16) __half g_mw1T[NLAYER * H * H];
__device__ __align__(16) __half g_mw2T[NLAYER * H * H];
__device__ __align__(16) float g_cl[NLAYER * H];
__device__ __align__(16) float g_pool[NB * H];
__device__ __align__(16) int g_src[NEDGES];
__device__ __align__(16) int g_dst[NEDGES];
__device__ int g_is64;

__device__ __forceinline__ void mma_f16(float* d, const uint32_t* a, const uint32_t* b) {
    asm volatile(
        "mma.sync.aligned.m16n8k16.row.col.f32.f16.f16.f32 "
        "{%0,%1,%2,%3}, {%4,%5,%6,%7}, {%8,%9}, {%0,%1,%2,%3};"
        : "+f"(d[0]), "+f"(d[1]), "+f"(d[2]), "+f"(d[3])
        : "r"(a[0]), "r"(a[1]), "r"(a[2]), "r"(a[3]), "r"(b[0]), "r"(b[1]));
}

__device__ __forceinline__ uint32_t pack_h2(float x, float y) {
    uint32_t u;
    asm("cvt.rn.f16x2.f32 %0, %1, %2;" : "=r"(u) : "f"(y), "f"(x));
    return u;
}

__device__ __forceinline__ uint32_t smem_u32(const void* p) {
    uint32_t a;
    asm("{ .reg .u64 t; cvta.to.shared.u64 t, %1; cvt.u32.u64 %0, t; }" : "=r"(a) : "l"(p));
    return a;
}

#define LDSM4(r0, r1, r2, r3, addr)                                            \
    asm volatile("ldmatrix.sync.aligned.m8n8.x4.shared.b16 {%0,%1,%2,%3}, [%4];" \
                 : "=r"(r0), "=r"(r1), "=r"(r2), "=r"(r3) : "r"(addr))

__device__ __forceinline__ void cp_async16(uint32_t saddr, const void* gptr) {
    asm volatile("cp.async.cg.shared.global [%0], [%1], 16;" :: "r"(saddr), "l"(gptr));
}
__device__ __forceinline__ void cp_commit() { asm volatile("cp.async.commit_group;"); }
__device__ __forceinline__ void cp_wait0() { asm volatile("cp.async.wait_group 0;" ::: "memory"); }

#define SAW 20       // smem row stride in words (16 data + 4 pad)
#define BUFB (128 * SAW * 4)  // one buffer in bytes

// ---- edge_index dtype detection + conversion ----
__global__ void detect_idx(const void* eidx) {
    if (threadIdx.x == 0) {
        const long long* p = (const long long*)eidx;
        int valid = 0;
        for (int i = 0; i < 256; i++) {
            long long v = p[i];
            if (v >= 0 && v < NNODES) valid++;
        }
        g_is64 = (valid == 256) ? 1 : 0;
    }
}

__global__ void conv_idx(const void* eidx) {
    int i = blockIdx.x * blockDim.x + threadIdx.x;
    if (i >= NEDGES) return;
    long long s, d;
    if (g_is64) {
        const long long* p = (const long long*)eidx;
        s = p[i]; d = p[NEDGES + i];
    } else {
        const int* p = (const int*)eidx;
        s = p[i]; d = p[NEDGES + i];
    }
    g_src[i] = (int)min((long long)(NNODES - 1), max(0LL, s));
    g_dst[i] = (int)min((long long)(NNODES - 1), max(0LL, d));
}

__global__ void prep_what(const float* __restrict__ em_w2, const float* __restrict__ lin_w) {
    int l = blockIdx.y, k = blockIdx.x, j = threadIdx.x;
    __shared__ float row[H];
    row[j] = em_w2[k * H + j];
    __syncthreads();
    const float* lw = lin_w + l * H * H;
    float acc = 0.f;
#pragma unroll 8
    for (int i = 0; i < H; i++) acc += row[i] * lw[i * H + j];
    g_WhatT[(l * H + j) * H + k] = __float2half(acc);
}

__global__ void prep_mwT(const float* __restrict__ m_w1, const float* __restrict__ m_w2) {
    int n = blockIdx.x, l = blockIdx.y, k = threadIdx.x;
    g_mw1T[(l * H + n) * H + k] = __float2half(m_w1[l * H * H + k * H + n]);
    g_mw2T[(l * H + n) * H + k] = __float2half(m_w2[l * H * H + k * H + n]);
}

__global__ void prep_cl(const float* __restrict__ em_b2, const float* __restrict__ lin_w,
                        const float* __restrict__ lin_b) {
    int l = blockIdx.x, j = threadIdx.x;
    const float* lw = lin_w + l * H * H;
    float acc = lin_b[l * H + j];
#pragma unroll 8
    for (int i = 0; i < H; i++) acc += em_b2[i] * lw[i * H + j];
    g_cl[l * H + j] = acc;
}

__global__ void node_init(const float* __restrict__ x, const int* __restrict__ a,
                          const float* __restrict__ np_w, const float* __restrict__ np_b) {
    __shared__ float w[4 * H];
    int tid = threadIdx.x;
    for (int i = tid; i < 4 * H; i += 256) w[i] = np_w[i];
    __syncthreads();
    float bb = np_b[tid];
    int node0 = blockIdx.x * 8;
    for (int i = 0; i < 8; i++) {
        int node = node0 + i;
        float v = x[node * 3] * w[tid] + x[node * 3 + 1] * w[H + tid] +
                  x[node * 3 + 2] * w[2 * H + tid] + (float)a[node] * w[3 * H + tid] + bb;
        v = fmaxf(v, 0.f);
        g_h[node * H + tid] = v;
        g_hh[node * H + tid] = __float2half(v);
    }
}

__global__ void zero_agg() {
    int idx = blockIdx.x * blockDim.x + threadIdx.x;
    float4 z = {0.f, 0.f, 0.f, 0.f};
    for (int i = idx; i < NNODES * H / 4; i += gridDim.x * blockDim.x)
        reinterpret_cast<float4*>(g_agg)[i] = z;
}

__global__ void zero_pool() {
    for (int i = threadIdx.x; i < NB * H; i += 256) g_pool[i] = 0.f;
}

// agg[dst] += relu(h[src] + t @ W_hat_l + c_l), t = relu(edge_attr@em_w1+em_b1)
// fp16 MMA + ldmatrix fragments, cp.async double-buffered.
__global__ void __launch_bounds__(256) edge_kernel(
    const float* __restrict__ edge_attr,
    const float* __restrict__ em_w1, const float* __restrict__ em_b1, int layer) {
    __shared__ uint32_t sA[2][128 * SAW];
    __shared__ uint32_t sB[2][128 * SAW];
    __shared__ float s_ea[128 * 4];
    __shared__ int s_src[128], s_dst[128];

    const int tid = threadIdx.x;
    const int wid = tid >> 5, lane = tid & 31;
    const int gid = lane >> 2, tg = lane & 3;
    const int e0 = blockIdx.x * 128, n0 = blockIdx.y * 128;
    const int wm = wid & 3, wn = wid >> 2;

    if (tid < 128) {
        reinterpret_cast<float4*>(s_ea)[tid] =
            reinterpret_cast<const float4*>(edge_attr)[e0 + tid];
        s_src[tid] = g_src[e0 + tid];
        s_dst[tid] = g_dst[e0 + tid];
    }
    const __half* Wt = g_WhatT + layer * H * H;

    const uint32_t aBase = smem_u32(sA);
    const uint32_t bBase = smem_u32(sB);
    const int tile = lane >> 3, li = lane & 7;
    const uint32_t laneA = (((tile & 1) * 8 + li) * SAW) * 4 + (tile >> 1) * 16;
    const uint32_t laneB = (((tile >> 1) * 8 + li) * SAW) * 4 + (tile & 1) * 16;

    float acc[2][8][4];
#pragma unroll
    for (int a = 0; a < 2; a++)
#pragma unroll
        for (int b = 0; b < 8; b++)
#pragma unroll
            for (int c = 0; c < 4; c++) acc[a][b][c] = 0.f;

    __syncthreads();

    const int kl = (tid & 15) * 2;
    const int trow0 = (tid >> 4) * 8;
    const int bn = tid >> 2, bj = tid & 3;

#define STAGE_B(c, buf)                                                              \
    do {                                                                             \
        const __half* src0 = Wt + (n0 + bn) * H + (c) * 32 + bj * 8;                 \
        cp_async16(bBase + (buf) * BUFB + (bn * SAW + bj * 4) * 4, src0);            \
        const __half* src1 = src0 + 64 * H;                                          \
        cp_async16(bBase + (buf) * BUFB + ((bn + 64) * SAW + bj * 4) * 4, src1);     \
        cp_commit();                                                                 \
    } while (0)

#define STAGE_A(c, buf)                                                              \
    do {                                                                             \
        int kg = (c) * 32 + kl;                                                      \
        float w0a = em_w1[kg], w1a = em_w1[H + kg], w2a = em_w1[2 * H + kg],         \
              w3a = em_w1[3 * H + kg];                                               \
        float w0b = em_w1[kg + 1], w1b = em_w1[H + kg + 1],                          \
              w2b = em_w1[2 * H + kg + 1], w3b = em_w1[3 * H + kg + 1];              \
        float ba = em_b1[kg], bb2 = em_b1[kg + 1];                                   \
        _Pragma("unroll")                                                            \
        for (int i = 0; i < 8; i++) {                                                \
            int r = trow0 + i;                                                       \
            float e0v = s_ea[r * 4], e1v = s_ea[r * 4 + 1],                          \
                  e2v = s_ea[r * 4 + 2], e3v = s_ea[r * 4 + 3];                      \
            float ta = fmaf(e0v, w0a, fmaf(e1v, w1a, fmaf(e2v, w2a, fmaf(e3v, w3a, ba)))); \
            float tb = fmaf(e0v, w0b, fmaf(e1v, w1b, fmaf(e2v, w2b, fmaf(e3v, w3b, bb2)))); \
            sA[buf][r * SAW + (kl >> 1)] = pack_h2(fmaxf(ta, 0.f), fmaxf(tb, 0.f));  \
        }                                                                            \
    } while (0)

    STAGE_B(0, 0);
    STAGE_A(0, 0);
    cp_wait0();
    __syncthreads();

    for (int c = 0; c < 8; c++) {
        int cur = c & 1, nxt = cur ^ 1;
        if (c < 7) {
            STAGE_B(c + 1, nxt);
            STAGE_A(c + 1, nxt);
        }
        uint32_t aBuf = aBase + cur * BUFB;
        uint32_t bBuf = bBase + cur * BUFB;
#pragma unroll
        for (int kk = 0; kk < 2; kk++) {
            uint32_t afr[2][4];
#pragma unroll
            for (int mt = 0; mt < 2; mt++) {
                uint32_t ad = aBuf + ((wm * 32 + mt * 16) * SAW) * 4 + kk * 32 + laneA;
                LDSM4(afr[mt][0], afr[mt][1], afr[mt][2], afr[mt][3], ad);
            }
#pragma unroll
            for (int ntp = 0; ntp < 4; ntp++) {
                uint32_t b0, b1, b2, b3;
                uint32_t bd = bBuf + ((wn * 64 + ntp * 16) * SAW) * 4 + kk * 32 + laneB;
                LDSM4(b0, b1, b2, b3, bd);
                uint32_t bA[2] = {b0, b1}, bB[2] = {b2, b3};
                mma_f16(acc[0][ntp * 2], afr[0], bA);
                mma_f16(acc[1][ntp * 2], afr[1], bA);
                mma_f16(acc[0][ntp * 2 + 1], afr[0], bB);
                mma_f16(acc[1][ntp * 2 + 1], afr[1], bB);
            }
        }
        if (c < 7) cp_wait0();
        __syncthreads();
    }
#undef STAGE_A
#undef STAGE_B

    const float* clp = g_cl + layer * H;
#pragma unroll
    for (int mt = 0; mt < 2; mt++) {
        int r0 = wm * 32 + mt * 16 + gid;
#pragma unroll
        for (int nt = 0; nt < 8; nt++) {
            float a0 = acc[mt][nt][0], a1 = acc[mt][nt][1];
            float a2 = acc[mt][nt][2], a3 = acc[mt][nt][3];
            float r0v = __shfl_xor_sync(0xffffffffu, a0, 1);
            float r1v = __shfl_xor_sync(0xffffffffu, a1, 1);
            float r2v = __shfl_xor_sync(0xffffffffu, a2, 1);
            float r3v = __shfl_xor_sync(0xffffffffu, a3, 1);
            int colb = n0 + wn * 64 + nt * 8 + (tg & 2) * 2;
            int rloc = (tg & 1) ? (r0 + 8) : r0;
            float4 ev;
            if (tg & 1) { ev.x = r2v; ev.y = r3v; ev.z = a2; ev.w = a3; }
            else        { ev.x = a0;  ev.y = a1;  ev.z = r0v; ev.w = r1v; }
            int src = s_src[rloc], dst = s_dst[rloc];
            float4 cv = *reinterpret_cast<const float4*>(clp + colb);
            uint2 hraw = *reinterpret_cast<const uint2*>(g_hh + src * H + colb);
            __half2 ha = *reinterpret_cast<__half2*>(&hraw.x);
            __half2 hb = *reinterpret_cast<__half2*>(&hraw.y);
            float2 fa = __half22float2(ha), fb = __half22float2(hb);
            float4 m;
            m.x = fmaxf(ev.x + cv.x + fa.x, 0.f);
            m.y = fmaxf(ev.y + cv.y + fa.y, 0.f);
            m.z = fmaxf(ev.z + cv.z + fb.x, 0.f);
            m.w = fmaxf(ev.w + cv.w + fb.y, 0.f);
            atomicAdd(reinterpret_cast<float4*>(g_agg + dst * H + colb), m);
        }
    }
}

// mode 0: A=h+agg, out u=relu(A@m_w1+b1); mode 1: A=u, out v=A@m_w2+b2
__global__ void __launch_bounds__(256) mlp_kernel(const __half* __restrict__ BwT,
                                                  const float* __restrict__ bias, int mode) {
    __shared__ uint32_t sA[128 * SAW];
    __shared__ uint32_t sB[128 * SAW];
    const int tid = threadIdx.x;
    const int wid = tid >> 5, lane = tid & 31;
    const int gid = lane >> 2, tg = lane & 3;
    const int m0 = blockIdx.x * 128, n0 = blockIdx.y * 128;
    const int wm = wid & 3, wn = wid >> 2;

    const uint32_t aBase = smem_u32(sA);
    const uint32_t bBase = smem_u32(sB);
    const int tile = lane >> 3, li = lane & 7;
    const uint32_t laneA = (((tile & 1) * 8 + li) * SAW) * 4 + (tile >> 1) * 16;
    const uint32_t laneB = (((tile >> 1) * 8 + li) * SAW) * 4 + (tile & 1) * 16;

    float acc[2][8][4];
#pragma unroll
    for (int a = 0; a < 2; a++)
#pragma unroll
        for (int b = 0; b < 8; b++)
#pragma unroll
            for (int c = 0; c < 4; c++) acc[a][b][c] = 0.f;

    for (int k0 = 0; k0 < H; k0 += 32) {
#pragma unroll
        for (int it = 0; it < 4; it++) {
            int flat = it * 256 + tid;
            int r = flat >> 3, q = flat & 7;
            int cc = q * 4;
            float4 av;
            if (mode == 0) {
                float4 hv = *reinterpret_cast<const float4*>(g_h + (m0 + r) * H + k0 + cc);
                float4 gv = *reinterpret_cast<const float4*>(g_agg + (m0 + r) * H + k0 + cc);
                av.x = hv.x + gv.x; av.y = hv.y + gv.y;
                av.z = hv.z + gv.z; av.w = hv.w + gv.w;
            } else {
                av = *reinterpret_cast<const float4*>(g_u + (m0 + r) * H + k0 + cc);
            }
            uint2 pk;
            pk.x = pack_h2(av.x, av.y);
            pk.y = pack_h2(av.z, av.w);
            *reinterpret_cast<uint2*>(sA + r * SAW + q * 2) = pk;
        }
#pragma unroll
        for (int it = 0; it < 2; it++) {
            int flat = it * 256 + tid;
            int n = flat >> 2, j = flat & 3;
            uint4 v = *reinterpret_cast<const uint4*>(BwT + (n0 + n) * H + k0 + j * 8);
            *reinterpret_cast<uint4*>(sB + n * SAW + j * 4) = v;
        }
        __syncthreads();
#pragma unroll
        for (int kk = 0; kk < 2; kk++) {
            uint32_t afr[2][4];
#pragma unroll
            for (int mt = 0; mt < 2; mt++) {
                uint32_t ad = aBase + ((wm * 32 + mt * 16) * SAW) * 4 + kk * 32 + laneA;
                LDSM4(afr[mt][0], afr[mt][1], afr[mt][2], afr[mt][3], ad);
            }
#pragma unroll
            for (int ntp = 0; ntp < 4; ntp++) {
                uint32_t b0, b1, b2, b3;
                uint32_t bd = bBase + ((wn * 64 + ntp * 16) * SAW) * 4 + kk * 32 + laneB;
                LDSM4(b0, b1, b2, b3, bd);
                uint32_t bA[2] = {b0, b1}, bB[2] = {b2, b3};
                mma_f16(acc[0][ntp * 2], afr[0], bA);
                mma_f16(acc[1][ntp * 2], afr[1], bA);
                mma_f16(acc[0][ntp * 2 + 1], afr[0], bB);
                mma_f16(acc[1][ntp * 2 + 1], afr[1], bB);
            }
        }
        __syncthreads();
    }

#pragma unroll
    for (int mt = 0; mt < 2; mt++) {
        int row = m0 + wm * 32 + mt * 16 + gid;
#pragma unroll
        for (int nt = 0; nt < 8; nt++) {
            int col = n0 + wn * 64 + nt * 8 + tg * 2;
            float b0v = bias[col], b1v = bias[col + 1];
            if (mode == 0) {
                float2 o0 = {fmaxf(acc[mt][nt][0] + b0v, 0.f),
                             fmaxf(acc[mt][nt][1] + b1v, 0.f)};
                *reinterpret_cast<float2*>(g_u + row * H + col) = o0;
                float2 o1 = {fmaxf(acc[mt][nt][2] + b0v, 0.f),
                             fmaxf(acc[mt][nt][3] + b1v, 0.f)};
                *reinterpret_cast<float2*>(g_u + (row + 8) * H + col) = o1;
            } else {
                float2 o0 = {acc[mt][nt][0] + b0v, acc[mt][nt][1] + b1v};
                *reinterpret_cast<float2*>(g_v + row * H + col) = o0;
                float2 o1 = {acc[mt][nt][2] + b0v, acc[mt][nt][3] + b1v};
                *reinterpret_cast<float2*>(g_v + (row + 8) * H + col) = o1;
            }
        }
    }
}

__global__ void ln_res_kernel(const float* __restrict__ ln_g_all,
                              const float* __restrict__ ln_b_all, int layer) {
    int row = blockIdx.x * 8 + (threadIdx.x >> 5);
    int lane = threadIdx.x & 31;
    int c0 = lane * 8;
    const float* vr = g_v + row * H;
    float4 v1 = *reinterpret_cast<const float4*>(vr + c0);
    float4 v2 = *reinterpret_cast<const float4*>(vr + c0 + 4);
    float s = (v1.x + v1.y) + (v1.z + v1.w) + (v2.x + v2.y) + (v2.z + v2.w);
    float ss = v1.x * v1.x + v1.y * v1.y + v1.z * v1.z + v1.w * v1.w +
               v2.x * v2.x + v2.y * v2.y + v2.z * v2.z + v2.w * v2.w;
#pragma unroll
    for (int o = 16; o > 0; o >>= 1) {
        s += __shfl_xor_sync(0xffffffffu, s, o);
        ss += __shfl_xor_sync(0xffffffffu, ss, o);
    }
    float mean = s * (1.f / H);
    float var = ss * (1.f / H) - mean * mean;
    float rstd = rsqrtf(var + 1e-5f);
    const float* gg = ln_g_all + layer * H;
    const float* bb = ln_b_all + layer * H;
    float4 g1 = *reinterpret_cast<const float4*>(gg + c0);
    float4 g2 = *reinterpret_cast<const float4*>(gg + c0 + 4);
    float4 b1 = *reinterpret_cast<const float4*>(bb + c0);
    float4 b2 = *reinterpret_cast<const float4*>(bb + c0 + 4);
    float* hr = g_h + row * H;
    float4 h1 = *reinterpret_cast<float4*>(hr + c0);
    float4 h2 = *reinterpret_cast<float4*>(hr + c0 + 4);
    h1.x += fmaxf((v1.x - mean) * rstd * g1.x + b1.x, 0.f);
    h1.y += fmaxf((v1.y - mean) * rstd * g1.y + b1.y, 0.f);
    h1.z += fmaxf((v1.z - mean) * rstd * g1.z + b1.z, 0.f);
    h1.w += fmaxf((v1.w - mean) * rstd * g1.w + b1.w, 0.f);
    h2.x += fmaxf((v2.x - mean) * rstd * g2.x + b2.x, 0.f);
    h2.y += fmaxf((v2.y - mean) * rstd * g2.y + b2.y, 0.f);
    h2.z += fmaxf((v2.z - mean) * rstd * g2.z + b2.z, 0.f);
    h2.w += fmaxf((v2.w - mean) * rstd * g2.w + b2.w, 0.f);
    *reinterpret_cast<float4*>(hr + c0) = h1;
    *reinterpret_cast<float4*>(hr + c0 + 4) = h2;
    uint4 hp;
    hp.x = pack_h2(h1.x, h1.y);
    hp.y = pack_h2(h1.z, h1.w);
    hp.z = pack_h2(h2.x, h2.y);
    hp.w = pack_h2(h2.z, h2.w);
    *reinterpret_cast<uint4*>(g_hh + row * H + c0) = hp;
}

__global__ void pool_kernel() {
    int b = blockIdx.x, ch = blockIdx.y, c = threadIdx.x;
    int base = b * NPER + ch * 128;
    float s = 0.f;
#pragma unroll 4
    for (int i = 0; i < 128; i++) s += g_h[(base + i) * H + c];
    atomicAdd(&g_pool[b * H + c], s);
}

__global__ void head_kernel(const float* __restrict__ hd_w1, const float* __restrict__ hd_b1,
                            const float* __restrict__ hd_w2, const float* __restrict__ hd_b2,
                            float* __restrict__ out) {
    __shared__ float gs[NB * H];
    __shared__ float red[8];
    int tid = threadIdx.x;
    int lane = tid & 31, wid = tid >> 5;
    for (int i = tid; i < NB * H; i += 256) gs[i] = g_pool[i] * (1.f / NPER);
    __syncthreads();
    float w2 = hd_w2[tid];
    float bb = hd_b1[tid];
    for (int b = 0; b < NB; b++) {
        float acc = bb;
#pragma unroll 8
        for (int i = 0; i < H; i++) acc += gs[b * H + i] * hd_w1[i * H + tid];
        float contrib = fmaxf(acc, 0.f) * w2;
#pragma unroll
        for (int o = 16; o > 0; o >>= 1) contrib += __shfl_xor_sync(0xffffffffu, contrib, o);
        if (lane == 0) red[wid] = contrib;
        __syncthreads();
        if (tid == 0) {
            float q = hd_b2[0];
            for (int w = 0; w < 8; w++) q += red[w];
            out[b] = q;
        }
        __syncthreads();
    }
}

extern "C" void kernel_launch(void* const* d_in, const int* in_sizes, int n_in,
                              void* d_out, int out_size) {
    const float* x         = (const float*)d_in[0];
    const float* edge_attr = (const float*)d_in[1];
    const void*  eidx      = (const void*)d_in[2];
    const int* a           = (const int*)d_in[3];
    const float* np_w  = (const float*)d_in[4];
    const float* np_b  = (const float*)d_in[5];
    const float* em_w1 = (const float*)d_in[6];
    const float* em_b1 = (const float*)d_in[7];
    const float* em_w2 = (const float*)d_in[8];
    const float* em_b2 = (const float*)d_in[9];
    const float* lin_w = (const float*)d_in[10];
    const float* lin_b = (const float*)d_in[11];
    const float* m_w1  = (const float*)d_in[12];
    const float* m_b1  = (const float*)d_in[13];
    const float* m_w2  = (const float*)d_in[14];
    const float* m_b2  = (const float*)d_in[15];
    const float* ln_g  = (const float*)d_in[16];
    const float* ln_b  = (const float*)d_in[17];
    const float* hd_w1 = (const float*)d_in[18];
    const float* hd_b1 = (const float*)d_in[19];
    const float* hd_w2 = (const float*)d_in[20];
    const float* hd_b2 = (const float*)d_in[21];
    float* out = (float*)d_out;

    __half* w1T; cudaGetSymbolAddress((void**)&w1T, g_mw1T);
    __half* w2T; cudaGetSymbolAddress((void**)&w2T, g_mw2T);

    detect_idx<<<1, 32>>>(eidx);
    conv_idx<<<NEDGES / 256, 256>>>(eidx);
    prep_what<<<dim3(H, NLAYER), 256>>>(em_w2, lin_w);
    prep_mwT<<<dim3(H, NLAYER), 256>>>(m_w1, m_w2);
    prep_cl<<<NLAYER, 256>>>(em_b2, lin_w, lin_b);
    node_init<<<NNODES / 8, 256>>>(x, a, np_w, np_b);

    for (int l = 0; l < NLAYER; l++) {
        zero_agg<<<1024, 256>>>();
        edge_kernel<<<dim3(NEDGES / 128, 2), 256>>>(edge_attr, em_w1, em_b1, l);
        mlp_kernel<<<dim3(NNODES / 128, 2), 256>>>(w1T + l * H * H, m_b1 + l * H, 0);
        mlp_kernel<<<dim3(NNODES / 128, 2), 256>>>(w2T + l * H * H, m_b2 + l * H, 1);
        ln_res_kernel<<<NNODES / 8, 256>>>(ln_g, ln_b, l);
    }

    zero_pool<<<1, 256>>>();
    pool_kernel<<<dim3(NB, NPER / 128), 256>>>();
    head_kernel<<<1, 256>>>(hd_w1, hd_b1, hd_w2, hd_b2, out);
}